// round 10
// baseline (speedup 1.0000x reference)
#include <cuda_runtime.h>
#include <math.h>

#define BSZ  1024
#define SLEN 512
#define TT   64
#define NW   2    // warps per block
#define CPW  2    // chains per warp (ILP)
#define KRN  6    // renormalize every KRN steps (exact pow-2, numerics-invariant)

__device__ double g_res[BSZ];
__device__ int    g_cnt[BSZ];
__device__ int    g_ticket;    // zero-init; last block resets to 0 (replay-safe)

static __device__ __forceinline__ unsigned long long pk2(float x, float y) {
    unsigned long long r;
    asm("mov.b64 %0, {%1, %2};" : "=l"(r) : "f"(x), "f"(y));
    return r;
}
static __device__ __forceinline__ float2 upk2(unsigned long long v) {
    float2 r;
    asm("mov.b64 {%0, %1}, %2;" : "=f"(r.x), "=f"(r.y) : "l"(v));
    return r;
}
static __device__ __forceinline__ unsigned long long ffma2(unsigned long long a,
                                                           unsigned long long b,
                                                           unsigned long long c) {
    unsigned long long d;
    asm("fma.rn.f32x2 %0, %1, %2, %3;" : "=l"(d) : "l"(a), "l"(b), "l"(c));
    return d;
}
static __device__ __forceinline__ unsigned long long fadd2(unsigned long long a,
                                                           unsigned long long b) {
    unsigned long long d;
    asm("add.rn.f32x2 %0, %1, %2;" : "=l"(d) : "l"(a), "l"(b));
    return d;
}
static __device__ __forceinline__ unsigned long long fmul2(unsigned long long a,
                                                           unsigned long long b) {
    unsigned long long d;
    asm("mul.rn.f32x2 %0, %1, %2;" : "=l"(d) : "l"(a), "l"(b));
    return d;
}

__global__ __launch_bounds__(NW * 32, 2)
void crf_forward(const float* __restrict__ e, const int* __restrict__ tags,
                 const unsigned char* __restrict__ mask,
                 const float* __restrict__ st, const float* __restrict__ et,
                 const float* __restrict__ tmat, float* __restrict__ out)
{
    // duplicated-p arrays, double buffered, per warp per chain
    __shared__ __align__(16) unsigned long long pd[NW][CPW][2][TT];
    __shared__ unsigned smw[NW][CPW][17];   // mask bit-words + zero pad
    __shared__ int s_t;

    const int w      = threadIdx.x >> 5;
    const int lane   = threadIdx.x & 31;
    const int chainA = (blockIdx.x * NW + w) * CPW;
    const int chainB = chainA + 1;
    const int c0 = 2 * lane, c1 = c0 + 1;   // this lane's two (adjacent) columns

    const float*         ebA = e    + (size_t)chainA * (SLEN * TT);
    const float*         ebB = e    + (size_t)chainB * (SLEN * TT);
    const int*           tbA = tags + chainA * SLEN;
    const int*           tbB = tags + chainB * SLEN;
    const unsigned char* mbA = mask + chainA * SLEN;
    const unsigned char* mbB = mask + chainB * SLEN;

    // ---- exp(transition) in registers (shared by both chains) ----
    unsigned long long Ep[TT];
#pragma unroll
    for (int i = 0; i < TT; ++i) {
        const float2 tv = *reinterpret_cast<const float2*>(&tmat[i * TT + c0]);
        Ep[i] = pk2(__expf(tv.x), __expf(tv.y));
    }

    // ---- tag-path score + mask count + mask bit-words (both chains) ----
    float scA = 0.f, scB = 0.f;
    int cnA = 0, cnB = 0;
#pragma unroll 4
    for (int k2 = 0; k2 < 16; ++k2) {
        int s = k2 * 32 + lane;
        int mA = mbA[s];
        int mB = mbB[s];
        unsigned bA = __ballot_sync(0xffffffffu, mA != 0);
        unsigned bB = __ballot_sync(0xffffffffu, mB != 0);
        if (lane == 0) { smw[w][0][k2] = bA; smw[w][1][k2] = bB; }
        cnA += mA; cnB += mB;
        if (s > 0 && mA) {
            int tp = tbA[s - 1], tn = tbA[s];
            scA += __ldg(&tmat[tp * TT + tn]) + ebA[s * TT + tn];
        }
        if (s > 0 && mB) {
            int tp = tbB[s - 1], tn = tbB[s];
            scB += __ldg(&tmat[tp * TT + tn]) + ebB[s * TT + tn];
        }
    }
    if (lane == 0) { smw[w][0][16] = 0u; smw[w][1][16] = 0u; }
#pragma unroll
    for (int off = 16; off; off >>= 1) {
        scA += __shfl_xor_sync(0xffffffffu, scA, off);
        scB += __shfl_xor_sync(0xffffffffu, scB, off);
        cnA += __shfl_xor_sync(0xffffffffu, cnA, off);
        cnB += __shfl_xor_sync(0xffffffffu, cnB, off);
    }
    float scoreA = scA + st[tbA[0]] + ebA[tbA[0]] + et[tbA[cnA - 1]];
    float scoreB = scB + st[tbB[0]] + ebB[tbB[0]] + et[tbB[cnB - 1]];

    // ---- forward-vector init (step 0), both chains ----
    float2 evA = *reinterpret_cast<const float2*>(ebA + c0);
    float2 evB = *reinterpret_cast<const float2*>(ebB + c0);
    float stx = st[c0], sty = st[c1];
    float nA0 = stx + evA.x, nA1 = sty + evA.y;
    float nB0 = stx + evB.x, nB1 = sty + evB.y;
    unsigned mxA = __reduce_max_sync(0xffffffffu, __float_as_uint(fmaxf(nA0, nA1) + 1024.0f));
    unsigned mxB = __reduce_max_sync(0xffffffffu, __float_as_uint(fmaxf(nB0, nB1) + 1024.0f));
    float baseA = __uint_as_float(mxA) - 1024.0f;   // offset keeps value positive for REDUX
    float baseB = __uint_as_float(mxB) - 1024.0f;
    float pA0 = __expf(nA0 - baseA), pA1 = __expf(nA1 - baseA);
    float pB0 = __expf(nB0 - baseB), pB1 = __expf(nB1 - baseB);
    *reinterpret_cast<ulonglong2*>(&pd[w][0][0][c0]) =
        make_ulonglong2(pk2(pA0, pA0), pk2(pA1, pA1));
    *reinterpret_cast<ulonglong2*>(&pd[w][1][0][c0]) =
        make_ulonglong2(pk2(pB0, pB0), pk2(pB1, pB1));
    int curA = 0, curB = 0;
    int EaccA = 0, EaccB = 0;
    int rcA = 0, rcB = 0;
    __syncwarp();

    // one double-step: both chains advance one step; single syncwarp
    auto step2 = [&](float2 ecA, unsigned mkA, float2 ecB, unsigned mkB) {
        unsigned long long FA = pk2(__expf(ecA.x), __expf(ecA.y));
        unsigned long long FB = pk2(__expf(ecB.x), __expf(ecB.y));
        const ulonglong2* rpA = reinterpret_cast<const ulonglong2*>(pd[w][0][curA]);
        const ulonglong2* rpB = reinterpret_cast<const ulonglong2*>(pd[w][1][curB]);
        unsigned long long aA0 = 0ull, aA1 = 0ull, aA2 = 0ull, aA3 = 0ull;
        unsigned long long aB0 = 0ull, aB1 = 0ull, aB2 = 0ull, aB3 = 0ull;
#pragma unroll
        for (int k = 0; k < 8; ++k) {
            ulonglong2 vA0 = rpA[4 * k],     vB0 = rpB[4 * k];
            ulonglong2 vA1 = rpA[4 * k + 1], vB1 = rpB[4 * k + 1];
            ulonglong2 vA2 = rpA[4 * k + 2], vB2 = rpB[4 * k + 2];
            ulonglong2 vA3 = rpA[4 * k + 3], vB3 = rpB[4 * k + 3];
            aA0 = ffma2(vA0.x, Ep[8 * k],     aA0);  aB0 = ffma2(vB0.x, Ep[8 * k],     aB0);
            aA1 = ffma2(vA0.y, Ep[8 * k + 1], aA1);  aB1 = ffma2(vB0.y, Ep[8 * k + 1], aB1);
            aA2 = ffma2(vA1.x, Ep[8 * k + 2], aA2);  aB2 = ffma2(vB1.x, Ep[8 * k + 2], aB2);
            aA3 = ffma2(vA1.y, Ep[8 * k + 3], aA3);  aB3 = ffma2(vB1.y, Ep[8 * k + 3], aB3);
            aA0 = ffma2(vA2.x, Ep[8 * k + 4], aA0);  aB0 = ffma2(vB2.x, Ep[8 * k + 4], aB0);
            aA1 = ffma2(vA2.y, Ep[8 * k + 5], aA1);  aB1 = ffma2(vB2.y, Ep[8 * k + 5], aB1);
            aA2 = ffma2(vA3.x, Ep[8 * k + 6], aA2);  aB2 = ffma2(vB3.x, Ep[8 * k + 6], aB2);
            aA3 = ffma2(vA3.y, Ep[8 * k + 7], aA3);  aB3 = ffma2(vB3.y, Ep[8 * k + 7], aB3);
        }
        float2 qA = upk2(fmul2(fadd2(fadd2(aA0, aA1), fadd2(aA2, aA3)), FA));
        float2 qB = upk2(fmul2(fadd2(fadd2(aB0, aB1), fadd2(aB2, aB3)), FB));
        // masked step -> keep old p (select, no branch)
        float qA0 = mkA ? qA.x : pA0,  qA1 = mkA ? qA.y : pA1;
        float qB0 = mkB ? qB.x : pB0,  qB1 = mkB ? qB.y : pB1;
        rcA += mkA ? 1 : 0;
        rcB += mkB ? 1 : 0;
        if (rcA >= KRN) {       // exact pow-2 renorm (valid regardless of mask)
            rcA = 0;
            unsigned mx = __reduce_max_sync(0xffffffffu, __float_as_uint(fmaxf(qA0, qA1)));
            int ke = (int)(mx >> 23) - 127;
            EaccA += ke;
            float rinv = __int_as_float((127 - ke) << 23);
            qA0 *= rinv; qA1 *= rinv;
        }
        if (rcB >= KRN) {
            rcB = 0;
            unsigned mx = __reduce_max_sync(0xffffffffu, __float_as_uint(fmaxf(qB0, qB1)));
            int ke = (int)(mx >> 23) - 127;
            EaccB += ke;
            float rinv = __int_as_float((127 - ke) << 23);
            qB0 *= rinv; qB1 *= rinv;
        }
        pA0 = qA0; pA1 = qA1; pB0 = qB0; pB1 = qB1;
        curA ^= 1; curB ^= 1;
        *reinterpret_cast<ulonglong2*>(&pd[w][0][curA][c0]) =
            make_ulonglong2(pk2(qA0, qA0), pk2(qA1, qA1));
        *reinterpret_cast<ulonglong2*>(&pd[w][1][curB][c0]) =
            make_ulonglong2(pk2(qB0, qB0), pk2(qB1, qB1));
        __syncwarp();
    };

    // ---- main loop: two steps per iter, prefetch distance 2 per chain ----
    float2 eA0 = *reinterpret_cast<const float2*>(ebA + 1 * TT + c0);
    float2 eA1 = *reinterpret_cast<const float2*>(ebA + 2 * TT + c0);
    float2 eB0 = *reinterpret_cast<const float2*>(ebB + 1 * TT + c0);
    float2 eB1 = *reinterpret_cast<const float2*>(ebB + 2 * TT + c0);
#pragma unroll 1
    for (int s = 1; s < SLEN; s += 2) {
        float2 cA0 = eA0, cA1 = eA1, cB0 = eB0, cB1 = eB1;
        unsigned wa0 = smw[w][0][s >> 5], wa1 = smw[w][0][(s >> 5) + 1];
        unsigned wb0 = smw[w][1][s >> 5], wb1 = smw[w][1][(s >> 5) + 1];
        unsigned bitsA = __funnelshift_r(wa0, wa1, s & 31);  // bit0=s, bit1=s+1
        unsigned bitsB = __funnelshift_r(wb0, wb1, s & 31);
        if (s + 2 < SLEN) {
            eA0 = *reinterpret_cast<const float2*>(ebA + (s + 2) * TT + c0);
            eB0 = *reinterpret_cast<const float2*>(ebB + (s + 2) * TT + c0);
        }
        if (s + 3 < SLEN) {
            eA1 = *reinterpret_cast<const float2*>(ebA + (s + 3) * TT + c0);
            eB1 = *reinterpret_cast<const float2*>(ebB + (s + 3) * TT + c0);
        }
        step2(cA0, bitsA & 1u, cB0, bitsB & 1u);
        if (s + 1 < SLEN)
            step2(cA1, bitsA & 2u, cB1, bitsB & 2u);
    }

    // ---- logZ, per-chain results ----
    float etx = __expf(et[c0]), ety = __expf(et[c1]);
    float zA = pA0 * etx + pA1 * ety;
    float zB = pB0 * etx + pB1 * ety;
#pragma unroll
    for (int off = 16; off; off >>= 1) {
        zA += __shfl_xor_sync(0xffffffffu, zA, off);
        zB += __shfl_xor_sync(0xffffffffu, zB, off);
    }
    if (lane == 0) {
        double logZA = (double)baseA + (double)EaccA * 0.6931471805599453094 + log((double)zA);
        double logZB = (double)baseB + (double)EaccB * 0.6931471805599453094 + log((double)zB);
        g_res[chainA] = (double)scoreA - logZA;
        g_res[chainB] = (double)scoreB - logZB;
        g_cnt[chainA] = cnA;
        g_cnt[chainB] = cnB;
    }

    // ---- last-block fused finalization (deterministic order) ----
    __syncthreads();
    if (threadIdx.x == 0) {
        __threadfence();
        s_t = atomicAdd(&g_ticket, 1);
    }
    __syncthreads();
    if (s_t == (int)gridDim.x - 1) {
        const int tid = threadIdx.x;       // 64 threads
        double acc = 0.0;
        int    cnt = 0;
#pragma unroll
        for (int i = 0; i < BSZ / (NW * 32); ++i) {   // 16 chains per thread
            int idx = tid + i * (NW * 32);
            acc += g_res[idx];
            cnt += g_cnt[idx];
        }
#pragma unroll
        for (int off = 16; off; off >>= 1) {
            acc += __shfl_xor_sync(0xffffffffu, acc, off);
            cnt += __shfl_xor_sync(0xffffffffu, cnt, off);
        }
        __shared__ double sacc[NW];
        __shared__ int    scnt[NW];
        if (lane == 0) { sacc[w] = acc; scnt[w] = cnt; }
        __syncthreads();
        if (tid == 0) {
            double ta = 0.0; int tc = 0;
#pragma unroll
            for (int i = 0; i < NW; ++i) { ta += sacc[i]; tc += scnt[i]; }
            out[0] = (float)(ta / (double)tc);
            g_ticket = 0;                      // reset for next graph replay
        }
    }
}

extern "C" void kernel_launch(void* const* d_in, const int* in_sizes, int n_in,
                              void* d_out, int out_size)
{
    const float*         e    = (const float*)d_in[0];
    const int*           tags = (const int*)d_in[1];
    const unsigned char* mask = (const unsigned char*)d_in[2];
    const float*         st   = (const float*)d_in[3];
    const float*         et   = (const float*)d_in[4];
    const float*         t    = (const float*)d_in[5];

    crf_forward<<<BSZ / (NW * CPW), NW * 32>>>(e, tags, mask, st, et, t, (float*)d_out);
}

// round 12
// speedup vs baseline: 2.6650x; 2.6650x over previous
#include <cuda_runtime.h>
#include <math.h>

#define BSZ  1024
#define SLEN 512
#define TT   64
#define NW   2    // warps (=independent chains) per block
#define KRN  6    // renormalize every KRN unmasked steps (exact pow-2, numerics-invariant)

__device__ double g_res[BSZ];
__device__ int    g_cnt[BSZ];
__device__ int    g_ticket;    // zero-init; last block resets to 0 (replay-safe)

static __device__ __forceinline__ unsigned long long pk2(float x, float y) {
    unsigned long long r;
    asm("mov.b64 %0, {%1, %2};" : "=l"(r) : "f"(x), "f"(y));
    return r;
}
static __device__ __forceinline__ float2 upk2(unsigned long long v) {
    float2 r;
    asm("mov.b64 {%0, %1}, %2;" : "=f"(r.x), "=f"(r.y) : "l"(v));
    return r;
}
static __device__ __forceinline__ unsigned long long ffma2(unsigned long long a,
                                                           unsigned long long b,
                                                           unsigned long long c) {
    unsigned long long d;
    asm("fma.rn.f32x2 %0, %1, %2, %3;" : "=l"(d) : "l"(a), "l"(b), "l"(c));
    return d;
}
static __device__ __forceinline__ unsigned long long fadd2(unsigned long long a,
                                                           unsigned long long b) {
    unsigned long long d;
    asm("add.rn.f32x2 %0, %1, %2;" : "=l"(d) : "l"(a), "l"(b));
    return d;
}

__global__ __launch_bounds__(NW * 32, 4)
void crf_forward(const float* __restrict__ e, const int* __restrict__ tags,
                 const unsigned char* __restrict__ mask,
                 const float* __restrict__ st, const float* __restrict__ et,
                 const float* __restrict__ tmat, float* __restrict__ out)
{
    // NON-duplicated p vector (64 floats = 16 x LDS.128), double buffered per warp
    __shared__ __align__(16) float pbuf[NW][2][TT];
    __shared__ unsigned smw[NW][17];   // mask bit-words (512 bits) + zero pad
    __shared__ int s_t;

    const int w     = threadIdx.x >> 5;
    const int lane  = threadIdx.x & 31;
    const int chain = blockIdx.x * NW + w;
    const int c0 = 2 * lane, c1 = c0 + 1;   // this lane's two (adjacent) columns

    const float*         eb = e    + (size_t)chain * (SLEN * TT);
    const int*           tb = tags + chain * SLEN;
    const unsigned char* mb = mask + chain * SLEN;

    // ---- exp(transition) in registers, per-column pair tables ----
    // Ea[m] = (E[2m][c0], E[2m+1][c0]),  Eb[m] = (E[2m][c1], E[2m+1][c1])
    unsigned long long Ea[32], Eb[32];
#pragma unroll
    for (int m = 0; m < 32; ++m) {
        const float2 t0v = *reinterpret_cast<const float2*>(&tmat[(2 * m)     * TT + c0]);
        const float2 t1v = *reinterpret_cast<const float2*>(&tmat[(2 * m + 1) * TT + c0]);
        Ea[m] = pk2(__expf(t0v.x), __expf(t1v.x));
        Eb[m] = pk2(__expf(t0v.y), __expf(t1v.y));
    }

    // ---- tag-path score + mask count + mask bit-words ----
    float scp = 0.f;
    int cntp = 0;
#pragma unroll 4
    for (int k2 = 0; k2 < 16; ++k2) {
        int s = k2 * 32 + lane;
        int m = mb[s];
        unsigned blt = __ballot_sync(0xffffffffu, m != 0);
        if (lane == 0) smw[w][k2] = blt;
        cntp += m;
        if (s > 0 && m) {
            int tp = tb[s - 1], tn = tb[s];
            scp += __ldg(&tmat[tp * TT + tn]) + eb[s * TT + tn];
        }
    }
    if (lane == 0) smw[w][16] = 0u;
#pragma unroll
    for (int off = 16; off; off >>= 1) {
        scp  += __shfl_xor_sync(0xffffffffu, scp, off);
        cntp += __shfl_xor_sync(0xffffffffu, cntp, off);
    }
    int   t0    = tb[0];
    int   tlast = tb[cntp - 1];
    float score = scp + st[t0] + eb[t0] + et[tlast];

    // ---- forward-vector init (step 0) ----
    float2 ev0 = *reinterpret_cast<const float2*>(eb + c0);
    float n0 = st[c0] + ev0.x;
    float n1 = st[c1] + ev0.y;
    float base = fmaxf(n0, n1);
#pragma unroll
    for (int off = 16; off; off >>= 1)
        base = fmaxf(base, __shfl_xor_sync(0xffffffffu, base, off));
    float p0 = __expf(n0 - base);
    float p1 = __expf(n1 - base);
    *reinterpret_cast<unsigned long long*>(&pbuf[w][0][c0]) = pk2(p0, p1);
    int cur  = 0;
    int Eacc = 0;   // accumulated power-of-two scale (exact)
    int rc   = 0;   // unmasked steps since last renorm
    __syncwarp();

    // one step: q_c = (sum_i p_i E[i][c]) * exp(e_c); exact pow-2 renorm every KRN
    auto do_step = [&](float2 ec, unsigned mk) {
        if (!mk) return;
        float F0 = __expf(ec.x);
        float F1 = __expf(ec.y);
        const ulonglong2* rp = reinterpret_cast<const ulonglong2*>(pbuf[w][cur]);
        unsigned long long x0 = 0ull, x1 = 0ull, x2 = 0ull, x3 = 0ull;
        unsigned long long y0 = 0ull, y1 = 0ull, y2 = 0ull, y3 = 0ull;
#pragma unroll
        for (int k = 0; k < 4; ++k) {
            // pairs m = 8k .. 8k+7 ; v.x = (p[2m],p[2m+1]) straight from LDS.128
            ulonglong2 v0 = rp[4 * k];
            ulonglong2 v1 = rp[4 * k + 1];
            ulonglong2 v2 = rp[4 * k + 2];
            ulonglong2 v3 = rp[4 * k + 3];
            x0 = ffma2(v0.x, Ea[8 * k],     x0);  y0 = ffma2(v0.x, Eb[8 * k],     y0);
            x1 = ffma2(v0.y, Ea[8 * k + 1], x1);  y1 = ffma2(v0.y, Eb[8 * k + 1], y1);
            x2 = ffma2(v1.x, Ea[8 * k + 2], x2);  y2 = ffma2(v1.x, Eb[8 * k + 2], y2);
            x3 = ffma2(v1.y, Ea[8 * k + 3], x3);  y3 = ffma2(v1.y, Eb[8 * k + 3], y3);
            x0 = ffma2(v2.x, Ea[8 * k + 4], x0);  y0 = ffma2(v2.x, Eb[8 * k + 4], y0);
            x1 = ffma2(v2.y, Ea[8 * k + 5], x1);  y1 = ffma2(v2.y, Eb[8 * k + 5], y1);
            x2 = ffma2(v3.x, Ea[8 * k + 6], x2);  y2 = ffma2(v3.x, Eb[8 * k + 6], y2);
            x3 = ffma2(v3.y, Ea[8 * k + 7], x3);  y3 = ffma2(v3.y, Eb[8 * k + 7], y3);
        }
        float2 qa = upk2(fadd2(fadd2(x0, x1), fadd2(x2, x3)));
        float2 qb = upk2(fadd2(fadd2(y0, y1), fadd2(y2, y3)));
        float q0 = (qa.x + qa.y) * F0;
        float q1 = (qb.x + qb.y) * F1;
        if (++rc >= KRN) {          // amortized exact pow-2 renorm (single REDUX)
            rc = 0;
            unsigned mxu = __reduce_max_sync(0xffffffffu,
                                             __float_as_uint(fmaxf(q0, q1)));
            int ke = (int)(mxu >> 23) - 127;                // floor(log2(max q))
            Eacc += ke;
            float rinv = __int_as_float((127 - ke) << 23);  // exact 2^-ke
            q0 *= rinv;
            q1 *= rinv;
        }
        p0 = q0;
        p1 = q1;
        cur ^= 1;
        *reinterpret_cast<unsigned long long*>(&pbuf[w][cur][c0]) = pk2(q0, q1);
        __syncwarp();
    };

    // ---- main loop: prefetch distance 4, unrolled x4, mask from bit-words ----
    float2 eA, eB, eC, eD;
    eA = *reinterpret_cast<const float2*>(eb + 1 * TT + c0);
    eB = *reinterpret_cast<const float2*>(eb + 2 * TT + c0);
    eC = *reinterpret_cast<const float2*>(eb + 3 * TT + c0);
    eD = *reinterpret_cast<const float2*>(eb + 4 * TT + c0);
#pragma unroll 1
    for (int s = 1; s < SLEN; s += 4) {
        float2 c_eA = eA, c_eB = eB, c_eC = eC, c_eD = eD;
        unsigned w0 = smw[w][s >> 5];
        unsigned w1 = smw[w][(s + 3) >> 5];
        unsigned mb4 = __funnelshift_r(w0, w1, s & 31);
        if (s + 4 < SLEN) eA = *reinterpret_cast<const float2*>(eb + (s + 4) * TT + c0);
        if (s + 5 < SLEN) eB = *reinterpret_cast<const float2*>(eb + (s + 5) * TT + c0);
        if (s + 6 < SLEN) eC = *reinterpret_cast<const float2*>(eb + (s + 6) * TT + c0);
        if (s + 7 < SLEN) eD = *reinterpret_cast<const float2*>(eb + (s + 7) * TT + c0);
        do_step(c_eA, mb4 & 1u);
        if (s + 1 < SLEN) do_step(c_eB, mb4 & 2u);
        if (s + 2 < SLEN) do_step(c_eC, mb4 & 4u);
        if (s + 3 < SLEN) do_step(c_eD, mb4 & 8u);
    }

    // ---- logZ, per-chain result ----
    float z = p0 * __expf(et[c0]) + p1 * __expf(et[c1]);
#pragma unroll
    for (int off = 16; off; off >>= 1)
        z += __shfl_xor_sync(0xffffffffu, z, off);
    if (lane == 0) {
        double logZ = (double)base + (double)Eacc * 0.6931471805599453094
                    + log((double)z);
        g_res[chain] = (double)score - logZ;
        g_cnt[chain] = cntp;
    }

    // ---- last-block fused finalization (deterministic order) ----
    __syncthreads();
    if (threadIdx.x == 0) {
        __threadfence();
        s_t = atomicAdd(&g_ticket, 1);
    }
    __syncthreads();
    if (s_t == (int)gridDim.x - 1) {
        const int tid = threadIdx.x;       // 64 threads
        double acc = 0.0;
        int    cnt = 0;
#pragma unroll
        for (int i = 0; i < BSZ / (NW * 32); ++i) {   // 16 chains per thread
            int idx = tid + i * (NW * 32);
            acc += g_res[idx];
            cnt += g_cnt[idx];
        }
#pragma unroll
        for (int off = 16; off; off >>= 1) {
            acc += __shfl_xor_sync(0xffffffffu, acc, off);
            cnt += __shfl_xor_sync(0xffffffffu, cnt, off);
        }
        __shared__ double sacc[NW];
        __shared__ int    scnt[NW];
        if (lane == 0) { sacc[w] = acc; scnt[w] = cnt; }
        __syncthreads();
        if (tid == 0) {
            double ta = 0.0; int tc = 0;
#pragma unroll
            for (int i = 0; i < NW; ++i) { ta += sacc[i]; tc += scnt[i]; }
            out[0] = (float)(ta / (double)tc);
            g_ticket = 0;                      // reset for next graph replay
        }
    }
}

extern "C" void kernel_launch(void* const* d_in, const int* in_sizes, int n_in,
                              void* d_out, int out_size)
{
    const float*         e    = (const float*)d_in[0];
    const int*           tags = (const int*)d_in[1];
    const unsigned char* mask = (const unsigned char*)d_in[2];
    const float*         st   = (const float*)d_in[3];
    const float*         et   = (const float*)d_in[4];
    const float*         t    = (const float*)d_in[5];

    crf_forward<<<BSZ / NW, NW * 32>>>(e, tags, mask, st, et, t, (float*)d_out);
}

// round 13
// speedup vs baseline: 2.7436x; 1.0295x over previous
#include <cuda_runtime.h>
#include <math.h>

#define BSZ  1024
#define SLEN 512
#define TT   64
#define NW   2    // warps (=independent chains) per block
#define KRN  6    // renormalize every KRN unmasked steps (exact pow-2, numerics-invariant)

__device__ double g_res[BSZ];
__device__ int    g_cnt[BSZ];
__device__ int    g_ticket;    // zero-init; last block resets to 0 (replay-safe)

static __device__ __forceinline__ unsigned long long pk2(float x, float y) {
    unsigned long long r;
    asm("mov.b64 %0, {%1, %2};" : "=l"(r) : "f"(x), "f"(y));
    return r;
}
static __device__ __forceinline__ float2 upk2(unsigned long long v) {
    float2 r;
    asm("mov.b64 {%0, %1}, %2;" : "=f"(r.x), "=f"(r.y) : "l"(v));
    return r;
}
static __device__ __forceinline__ unsigned long long ffma2(unsigned long long a,
                                                           unsigned long long b,
                                                           unsigned long long c) {
    unsigned long long d;
    asm("fma.rn.f32x2 %0, %1, %2, %3;" : "=l"(d) : "l"(a), "l"(b), "l"(c));
    return d;
}
static __device__ __forceinline__ unsigned long long fadd2(unsigned long long a,
                                                           unsigned long long b) {
    unsigned long long d;
    asm("add.rn.f32x2 %0, %1, %2;" : "=l"(d) : "l"(a), "l"(b));
    return d;
}

__global__ __launch_bounds__(NW * 32, 4)
void crf_forward(const float* __restrict__ e, const int* __restrict__ tags,
                 const unsigned char* __restrict__ mask,
                 const float* __restrict__ st, const float* __restrict__ et,
                 const float* __restrict__ tmat, float* __restrict__ out)
{
    __shared__ unsigned smw[NW][17];   // mask bit-words (512 bits) + zero pad
    __shared__ int s_t;

    const int w     = threadIdx.x >> 5;
    const int lane  = threadIdx.x & 31;
    const int chain = blockIdx.x * NW + w;
    const int c0 = 2 * lane, c1 = c0 + 1;   // this lane's two (adjacent) columns

    const float*         eb = e    + (size_t)chain * (SLEN * TT);
    const int*           tb = tags + chain * SLEN;
    const unsigned char* mb = mask + chain * SLEN;

    // ---- exp(transition) in registers, per-column pair tables ----
    // Ea[m] = (E[2m][c0], E[2m+1][c0]),  Eb[m] = (E[2m][c1], E[2m+1][c1])
    unsigned long long Ea[32], Eb[32];
#pragma unroll
    for (int m = 0; m < 32; ++m) {
        const float2 t0v = *reinterpret_cast<const float2*>(&tmat[(2 * m)     * TT + c0]);
        const float2 t1v = *reinterpret_cast<const float2*>(&tmat[(2 * m + 1) * TT + c0]);
        Ea[m] = pk2(__expf(t0v.x), __expf(t1v.x));
        Eb[m] = pk2(__expf(t0v.y), __expf(t1v.y));
    }

    // ---- tag-path score + mask count + mask bit-words ----
    float scp = 0.f;
    int cntp = 0;
#pragma unroll 4
    for (int k2 = 0; k2 < 16; ++k2) {
        int s = k2 * 32 + lane;
        int m = mb[s];
        unsigned blt = __ballot_sync(0xffffffffu, m != 0);
        if (lane == 0) smw[w][k2] = blt;
        cntp += m;
        if (s > 0 && m) {
            int tp = tb[s - 1], tn = tb[s];
            scp += __ldg(&tmat[tp * TT + tn]) + eb[s * TT + tn];
        }
    }
    if (lane == 0) smw[w][16] = 0u;
#pragma unroll
    for (int off = 16; off; off >>= 1) {
        scp  += __shfl_xor_sync(0xffffffffu, scp, off);
        cntp += __shfl_xor_sync(0xffffffffu, cntp, off);
    }
    int   t0    = tb[0];
    int   tlast = tb[cntp - 1];
    float score = scp + st[t0] + eb[t0] + et[tlast];

    // ---- forward-vector init (step 0) ----
    float2 ev0 = *reinterpret_cast<const float2*>(eb + c0);
    float n0 = st[c0] + ev0.x;
    float n1 = st[c1] + ev0.y;
    float base = fmaxf(n0, n1);
#pragma unroll
    for (int off = 16; off; off >>= 1)
        base = fmaxf(base, __shfl_xor_sync(0xffffffffu, base, off));
    // p lives ONLY in registers: pq = (p[c0], p[c1]) on this lane
    unsigned long long pq = pk2(__expf(n0 - base), __expf(n1 - base));
    int   Eacc = 0;     // accumulated power-of-two scale (exact)
    int   rc   = 0;     // unmasked steps since last renorm
    float pend = 1.0f;  // deferred exact 2^-ke, folded into next step's F
    __syncwarp();       // smw visibility

    // one step: q_c = (sum_i p_i E[i][c]) * exp(e_c) * pend; p via SHFL broadcast
    auto do_step = [&](float2 ec, unsigned mk) {
        if (!mk) return;
        float F0 = __expf(ec.x) * pend;
        float F1 = __expf(ec.y) * pend;
        pend = 1.0f;
        unsigned long long x0 = 0ull, x1 = 0ull, x2 = 0ull, x3 = 0ull;
        unsigned long long y0 = 0ull, y1 = 0ull, y2 = 0ull, y3 = 0ull;
#pragma unroll
        for (int m = 0; m < 32; m += 4) {
            unsigned long long u0 = __shfl_sync(0xffffffffu, pq, m);
            unsigned long long u1 = __shfl_sync(0xffffffffu, pq, m + 1);
            unsigned long long u2 = __shfl_sync(0xffffffffu, pq, m + 2);
            unsigned long long u3 = __shfl_sync(0xffffffffu, pq, m + 3);
            x0 = ffma2(u0, Ea[m],     x0);  y0 = ffma2(u0, Eb[m],     y0);
            x1 = ffma2(u1, Ea[m + 1], x1);  y1 = ffma2(u1, Eb[m + 1], y1);
            x2 = ffma2(u2, Ea[m + 2], x2);  y2 = ffma2(u2, Eb[m + 2], y2);
            x3 = ffma2(u3, Ea[m + 3], x3);  y3 = ffma2(u3, Eb[m + 3], y3);
        }
        float2 qa = upk2(fadd2(fadd2(x0, x1), fadd2(x2, x3)));
        float2 qb = upk2(fadd2(fadd2(y0, y1), fadd2(y2, y3)));
        float q0 = (qa.x + qa.y) * F0;
        float q1 = (qb.x + qb.y) * F1;
        pq = pk2(q0, q1);               // ready for next step's shfls immediately
        if (++rc >= KRN) {              // renorm measured here, applied next step
            rc = 0;
            unsigned mxu = __reduce_max_sync(0xffffffffu,
                                             __float_as_uint(fmaxf(q0, q1)));
            int ke = (int)(mxu >> 23) - 127;               // floor(log2(max q))
            Eacc += ke;
            pend = __int_as_float((127 - ke) << 23);       // exact 2^-ke
        }
    };

    // ---- main loop: prefetch distance 4, unrolled x4, mask from bit-words ----
    float2 eA, eB, eC, eD;
    eA = *reinterpret_cast<const float2*>(eb + 1 * TT + c0);
    eB = *reinterpret_cast<const float2*>(eb + 2 * TT + c0);
    eC = *reinterpret_cast<const float2*>(eb + 3 * TT + c0);
    eD = *reinterpret_cast<const float2*>(eb + 4 * TT + c0);
#pragma unroll 1
    for (int s = 1; s < SLEN; s += 4) {
        float2 c_eA = eA, c_eB = eB, c_eC = eC, c_eD = eD;
        unsigned w0 = smw[w][s >> 5];
        unsigned w1 = smw[w][(s + 3) >> 5];
        unsigned mb4 = __funnelshift_r(w0, w1, s & 31);
        if (s + 4 < SLEN) eA = *reinterpret_cast<const float2*>(eb + (s + 4) * TT + c0);
        if (s + 5 < SLEN) eB = *reinterpret_cast<const float2*>(eb + (s + 5) * TT + c0);
        if (s + 6 < SLEN) eC = *reinterpret_cast<const float2*>(eb + (s + 6) * TT + c0);
        if (s + 7 < SLEN) eD = *reinterpret_cast<const float2*>(eb + (s + 7) * TT + c0);
        do_step(c_eA, mb4 & 1u);
        if (s + 1 < SLEN) do_step(c_eB, mb4 & 2u);
        if (s + 2 < SLEN) do_step(c_eC, mb4 & 4u);
        if (s + 3 < SLEN) do_step(c_eD, mb4 & 8u);
    }

    // ---- logZ, per-chain result (apply any still-pending exact scale) ----
    float2 pf = upk2(pq);
    float z = (pf.x * __expf(et[c0]) + pf.y * __expf(et[c1])) * pend;
#pragma unroll
    for (int off = 16; off; off >>= 1)
        z += __shfl_xor_sync(0xffffffffu, z, off);
    if (lane == 0) {
        double logZ = (double)base + (double)Eacc * 0.6931471805599453094
                    + log((double)z);
        g_res[chain] = (double)score - logZ;
        g_cnt[chain] = cntp;
    }

    // ---- last-block fused finalization (deterministic order) ----
    __syncthreads();
    if (threadIdx.x == 0) {
        __threadfence();
        s_t = atomicAdd(&g_ticket, 1);
    }
    __syncthreads();
    if (s_t == (int)gridDim.x - 1) {
        const int tid = threadIdx.x;       // 64 threads
        double acc = 0.0;
        int    cnt = 0;
#pragma unroll
        for (int i = 0; i < BSZ / (NW * 32); ++i) {   // 16 chains per thread
            int idx = tid + i * (NW * 32);
            acc += g_res[idx];
            cnt += g_cnt[idx];
        }
#pragma unroll
        for (int off = 16; off; off >>= 1) {
            acc += __shfl_xor_sync(0xffffffffu, acc, off);
            cnt += __shfl_xor_sync(0xffffffffu, cnt, off);
        }
        __shared__ double sacc[NW];
        __shared__ int    scnt[NW];
        if (lane == 0) { sacc[w] = acc; scnt[w] = cnt; }
        __syncthreads();
        if (tid == 0) {
            double ta = 0.0; int tc = 0;
#pragma unroll
            for (int i = 0; i < NW; ++i) { ta += sacc[i]; tc += scnt[i]; }
            out[0] = (float)(ta / (double)tc);
            g_ticket = 0;                      // reset for next graph replay
        }
    }
}

extern "C" void kernel_launch(void* const* d_in, const int* in_sizes, int n_in,
                              void* d_out, int out_size)
{
    const float*         e    = (const float*)d_in[0];
    const int*           tags = (const int*)d_in[1];
    const unsigned char* mask = (const unsigned char*)d_in[2];
    const float*         st   = (const float*)d_in[3];
    const float*         et   = (const float*)d_in[4];
    const float*         t    = (const float*)d_in[5];

    crf_forward<<<BSZ / NW, NW * 32>>>(e, tags, mask, st, et, t, (float*)d_out);
}